// round 5
// baseline (speedup 1.0000x reference)
#include <cuda_runtime.h>
#include <math.h>

#define Nn 10000
#define Ee 320000
#define K1H 216          // per-head K for layer-1 GEMM
#define LDA1 (4 * K1H)   // 864
#define K2P 1376

// ---------------- static scratch ----------------
__device__ int   d_src[Ee], d_dst[Ee], d_et[Ee], d_nt[Nn];
__device__ int   d_deg[Nn], d_off[Nn + 1], d_cur[Nn];
__device__ int   d_eid[Ee], d_srcS[Ee], d_etS[Ee];
__device__ float d_se1[Ee * 4], d_se2[Ee * 4];
__device__ float d_ssrc[Nn * 4], d_sdst[Nn * 4];
__device__ float d_u1[Nn * 64], d_u2[Nn * 256], d_h1[Nn * 256];
__device__ float d_v1[(size_t)Nn * LDA1], d_v2[(size_t)Nn * K2P];
__device__ float d_wsrc1[256], d_wdst1[256], d_wae1[256], d_etd1[22 * 4];
__device__ float d_wsrc2[1024], d_wdst2[1024], d_wae2[256], d_etd2[22 * 4];
__device__ float d_W1h[4 * K1H * 64], d_W2cat[K2P * 256];

__device__ __forceinline__ float lrelu(float v) { return v > 0.f ? v : 0.2f * v; }
__device__ __forceinline__ float comp4(float4 v, int h) {
    return h == 0 ? v.x : (h == 1 ? v.y : (h == 2 ? v.z : v.w));
}
__device__ __forceinline__ int ldidx(const void* p, long long i, int is64) {
    return is64 ? (int)((const long long*)p)[i] : ((const int*)p)[i];
}
__device__ __forceinline__ unsigned long long dup2(float x) {
    unsigned long long r;
    asm("mov.b64 %0, {%1, %1};" : "=l"(r) : "r"(__float_as_uint(x)));
    return r;
}
__device__ __forceinline__ void fma2(unsigned long long& d, unsigned long long a,
                                     unsigned long long b) {
    asm("fma.rn.f32x2 %0, %1, %2, %0;" : "+l"(d) : "l"(a), "l"(b));
}

// per-block int64 detection from node_type buffer (safe: samples words < Nn)
__device__ __forceinline__ int block_is64(const unsigned int* w) {
    int t = threadIdx.x;
    int bad = 0;
    if (t < 128) bad = (w[2 * (t * 39) + 1] != 0u);
    return __syncthreads_or(bad) ? 0 : 1;
}

// ---------------- K1: fused preprocessing ----------------
#define PRE_CONV 1250
#define PRE_PW1  (PRE_CONV + 216)
#define PRE_PW2  (PRE_PW1 + 1376)
#define PRE_TOT  (PRE_PW2 + 13)

__global__ void k_pre(const void* ei, const void* ntp, const void* etp,
                      const float* W1, const float* as1, const float* ad1,
                      const float* We1, const float* ag1, const float* etb1,
                      const float* W2, const float* as2, const float* ad2,
                      const float* We2, const float* ag2, const float* etb2,
                      const float* res1) {
    int b = blockIdx.x, t = threadIdx.x;
    if (b < PRE_CONV) {
        int is64 = block_is64((const unsigned int*)ntp);
        int e = b * 256 + t;
        if (e < Ee) {
            int s = ldidx(ei, e, is64);
            int d2 = ldidx(ei, (long long)Ee + e, is64);
            d_src[e] = s; d_dst[e] = d2; d_et[e] = ldidx(etp, e, is64);
            atomicAdd(&d_deg[d2], 1);
        }
        if (b < 40) { int i = b * 256 + t; if (i < Nn) d_nt[i] = ldidx(ntp, i, is64); }
    } else if (b < PRE_PW1) {
        int j = (b - PRE_CONV) * 256 + t;  // < 55296
        int c = j & 63, hk = j >> 6, h = hk / K1H, k = hk - h * K1H;
        float v = 0.f;
        if (k < 64) v = W1[k * 256 + h * 64 + c];
        else if (k < 128) v = We1[(k - 64) * 256 + h * 64 + c];
        else if (k < 150) v = etb1[(k - 128) * 256 + h * 64 + c];
        else if (k < 214) v = res1[(k - 150) * 256 + h * 64 + c];
        d_W1h[j] = v;
    } else if (b < PRE_PW2) {
        int j = (b - PRE_PW1) * 256 + t;
        int col = j & 255, r = j >> 8;
        float v = 0.f;
        if (r < 1024) { int h = r >> 8, k = r & 255; v = W2[k * 1024 + h * 256 + col] * 0.25f; }
        else if (r < 1280) { int rr = r - 1024, h = rr >> 6, k = rr & 63; v = We2[k * 1024 + h * 256 + col] * 0.25f; }
        else if (r < 1368) { int rr = r - 1280, h = rr / 22, tt = rr % 22; v = etb2[tt * 1024 + h * 256 + col] * 0.25f; }
        d_W2cat[j] = v;
    } else {
        int j = (b - PRE_PW2) * 256 + t;
        if (j < 256) {
            int h = j >> 6, k = j & 63; float s = 0.f;
            for (int c = 0; c < 64; c++) s += W1[k * 256 + h * 64 + c] * as1[h * 64 + c];
            d_wsrc1[j] = s;
        } else if (j < 512) {
            int jj = j - 256, h = jj >> 6, k = jj & 63; float s = 0.f;
            for (int c = 0; c < 64; c++) s += W1[k * 256 + h * 64 + c] * ad1[h * 64 + c];
            d_wdst1[jj] = s;
        } else if (j < 768) {
            int jj = j - 512, h = jj >> 6, k = jj & 63; float s = 0.f;
            for (int c = 0; c < 64; c++) s += We1[k * 256 + h * 64 + c] * ag1[h * 64 + c];
            d_wae1[jj] = s;
        } else if (j < 856) {
            int jj = j - 768, tt = jj >> 2, h = jj & 3; float s = 0.f;
            for (int c = 0; c < 64; c++) s += etb1[tt * 256 + h * 64 + c] * ag1[h * 64 + c];
            d_etd1[jj] = s;
        } else if (j < 1880) {
            int jj = j - 856, h = jj >> 8, k = jj & 255; float s = 0.f;
            for (int c = 0; c < 256; c++) s += W2[k * 1024 + h * 256 + c] * as2[h * 256 + c];
            d_wsrc2[jj] = s;
        } else if (j < 2904) {
            int jj = j - 1880, h = jj >> 8, k = jj & 255; float s = 0.f;
            for (int c = 0; c < 256; c++) s += W2[k * 1024 + h * 256 + c] * ad2[h * 256 + c];
            d_wdst2[jj] = s;
        } else if (j < 3160) {
            int jj = j - 2904, h = jj >> 6, k = jj & 63; float s = 0.f;
            for (int c = 0; c < 256; c++) s += We2[k * 1024 + h * 256 + c] * ag2[h * 256 + c];
            d_wae2[jj] = s;
        } else if (j < 3248) {
            int jj = j - 3160, tt = jj >> 2, h = jj & 3; float s = 0.f;
            for (int c = 0; c < 256; c++) s += etb2[tt * 1024 + h * 256 + c] * ag2[h * 256 + c];
            d_etd2[jj] = s;
        }
    }
}

// ---------------- K2: scan (+ zero d_deg for next invocation) ----------------
__global__ void k_scan() {
    __shared__ int wsum[32];
    int t = threadIdx.x, base = t * 10, loc[10], sum = 0;
#pragma unroll
    for (int ii = 0; ii < 10; ii++) {
        int i = base + ii;
        int d = (i < Nn) ? d_deg[i] : 0;
        loc[ii] = d; sum += d;
    }
    int lane = t & 31, w = t >> 5;
    int v = sum;
#pragma unroll
    for (int o = 1; o < 32; o <<= 1) {
        int u = __shfl_up_sync(0xffffffffu, v, o);
        if (lane >= o) v += u;
    }
    if (lane == 31) wsum[w] = v;
    __syncthreads();
    if (w == 0) {
        int s = wsum[lane];
#pragma unroll
        for (int o = 1; o < 32; o <<= 1) {
            int u = __shfl_up_sync(0xffffffffu, s, o);
            if (lane >= o) s += u;
        }
        wsum[lane] = s;
    }
    __syncthreads();
    int run = v - sum + (w ? wsum[w - 1] : 0);
#pragma unroll
    for (int ii = 0; ii < 10; ii++) {
        int i = base + ii;
        if (i < Nn) { d_off[i] = run; d_cur[i] = run; d_deg[i] = 0; run += loc[ii]; }
        else if (i == Nn) d_off[Nn] = run;
    }
}

// ---------------- nscore body (shared by layer1-in-mid and layer2 kernel) -----
__device__ __forceinline__ void nscore_one(int gw, int lane, const float* xin,
                                           const float* ntemb, int K,
                                           const float* ws, const float* wd, float* u) {
    int nt = d_nt[gw];
    float ps[4] = {0, 0, 0, 0}, pd[4] = {0, 0, 0, 0};
    for (int k = lane; k < K; k += 32) {
        float v = xin[gw * K + k] + ntemb[nt * K + k];
        u[gw * K + k] = v;
#pragma unroll
        for (int h = 0; h < 4; h++) { ps[h] += v * ws[h * K + k]; pd[h] += v * wd[h * K + k]; }
    }
#pragma unroll
    for (int h = 0; h < 4; h++)
        for (int o = 16; o > 0; o >>= 1) {
            ps[h] += __shfl_xor_sync(0xffffffffu, ps[h], o);
            pd[h] += __shfl_xor_sync(0xffffffffu, pd[h], o);
        }
    if (lane == 0)
#pragma unroll
        for (int h = 0; h < 4; h++) { d_ssrc[gw * 4 + h] = ps[h]; d_sdst[gw * 4 + h] = pd[h]; }
}

// ---------------- K3: fused scatter + nscore1 + edgescore(original order) -----
#define MID_SCAT 1250
#define MID_NS   (MID_SCAT + 1250)
#define MID_TOT  (MID_NS + 40000)

__global__ void k_mid(const float* __restrict__ ea, const float* __restrict__ x,
                      const float* __restrict__ nte1) {
    int b = blockIdx.x, t = threadIdx.x;
    if (b < MID_SCAT) {
        int e = b * 256 + t;
        if (e < Ee) {
            int p = atomicAdd(&d_cur[d_dst[e]], 1);
            d_eid[p] = e; d_srcS[p] = d_src[e]; d_etS[p] = d_et[e];
        }
    } else if (b < MID_NS) {
        int gw = (b - MID_SCAT) * 8 + (t >> 5);
        if (gw < Nn) nscore_one(gw, t & 31, x, nte1, 64, d_wsrc1, d_wdst1, d_u1);
    } else {
        int e = (b - MID_NS) * 8 + (t >> 5);
        int lane = t & 31;
        float a0 = ea[(size_t)e * 64 + lane];
        float a1 = ea[(size_t)e * 64 + 32 + lane];
        float dd1[4], dd2[4];
#pragma unroll
        for (int h = 0; h < 4; h++) {
            dd1[h] = a0 * d_wae1[h * 64 + lane] + a1 * d_wae1[h * 64 + 32 + lane];
            dd2[h] = a0 * d_wae2[h * 64 + lane] + a1 * d_wae2[h * 64 + 32 + lane];
            for (int o = 16; o > 0; o >>= 1) {
                dd1[h] += __shfl_xor_sync(0xffffffffu, dd1[h], o);
                dd2[h] += __shfl_xor_sync(0xffffffffu, dd2[h], o);
            }
        }
        if (lane == 0) {
            int et = d_et[e];
#pragma unroll
            for (int h = 0; h < 4; h++) {
                d_se1[e * 4 + h] = dd1[h] + d_etd1[et * 4 + h];
                d_se2[e * 4 + h] = dd2[h] + d_etd2[et * 4 + h];
            }
        }
    }
}

// ---------------- block reductions (warp-shuffle, 2 syncs) ----------------
__device__ __forceinline__ float4 blockMax4(float4 v, float4* sh8, int tid) {
#pragma unroll
    for (int o = 16; o > 0; o >>= 1) {
        v.x = fmaxf(v.x, __shfl_xor_sync(0xffffffffu, v.x, o));
        v.y = fmaxf(v.y, __shfl_xor_sync(0xffffffffu, v.y, o));
        v.z = fmaxf(v.z, __shfl_xor_sync(0xffffffffu, v.z, o));
        v.w = fmaxf(v.w, __shfl_xor_sync(0xffffffffu, v.w, o));
    }
    if ((tid & 31) == 0) sh8[tid >> 5] = v;
    __syncthreads();
    if (tid == 0) {
        float4 r = sh8[0];
#pragma unroll
        for (int w = 1; w < 8; w++) {
            float4 b = sh8[w];
            r.x = fmaxf(r.x, b.x); r.y = fmaxf(r.y, b.y);
            r.z = fmaxf(r.z, b.z); r.w = fmaxf(r.w, b.w);
        }
        sh8[0] = r;
    }
    __syncthreads();
    return sh8[0];
}
__device__ __forceinline__ float4 blockSum4(float4 v, float4* sh8, int tid) {
#pragma unroll
    for (int o = 16; o > 0; o >>= 1) {
        v.x += __shfl_xor_sync(0xffffffffu, v.x, o);
        v.y += __shfl_xor_sync(0xffffffffu, v.y, o);
        v.z += __shfl_xor_sync(0xffffffffu, v.z, o);
        v.w += __shfl_xor_sync(0xffffffffu, v.w, o);
    }
    if ((tid & 31) == 0) sh8[tid >> 5] = v;
    __syncthreads();
    if (tid == 0) {
        float4 r = sh8[0];
#pragma unroll
        for (int w = 1; w < 8; w++) {
            float4 b = sh8[w];
            r.x += b.x; r.y += b.y; r.z += b.z; r.w += b.w;
        }
        sh8[0] = r;
    }
    __syncthreads();
    return sh8[0];
}

__device__ __forceinline__ float4 logit4(float4 ss, float4 sd, float4 se) {
    float4 l;
    l.x = lrelu(ss.x + sd.x + se.x); l.y = lrelu(ss.y + sd.y + se.y);
    l.z = lrelu(ss.z + sd.z + se.z); l.w = lrelu(ss.w + sd.w + se.w);
    return l;
}

// ---------------- K4: layer-1 attention (single-pass softmax) ----------------
__global__ void k_attn1(const float* __restrict__ ea, const float* __restrict__ x) {
    int n = blockIdx.x, tid = threadIdx.x;
    __shared__ float4 sh8[8];
    __shared__ float4 aSh[256];
    __shared__ int srcSh[256], eidSh[256], etSh[256];
    __shared__ float acct[88];
    if (tid < 88) acct[tid] = 0.f;
    int beg = d_off[n], end = d_off[n + 1], nE = end - beg;
    int h = tid >> 6, c = tid & 63;
    float ax = 0.f, ae = 0.f;
    const float4* ssrc4 = (const float4*)d_ssrc;
    const float4* se4 = (const float4*)d_se1;
    if (nE > 0 && nE <= 256) {
        float4 sd = ((const float4*)d_sdst)[n];
        float4 l = make_float4(-1e30f, -1e30f, -1e30f, -1e30f);
        if (tid < nE) {
            int i = beg + tid, s = d_srcS[i], e = d_eid[i];
            srcSh[tid] = s; eidSh[tid] = e; etSh[tid] = d_etS[i];
            l = logit4(ssrc4[s], sd, se4[e]);
        }
        float4 m = blockMax4(l, sh8, tid);
        float4 p = make_float4(0, 0, 0, 0);
        if (tid < nE) {
            p.x = __expf(l.x - m.x); p.y = __expf(l.y - m.y);
            p.z = __expf(l.z - m.z); p.w = __expf(l.w - m.w);
        }
        float4 den = blockSum4(p, sh8, tid);
        if (tid < nE) {
            p.x /= (den.x + 1e-16f); p.y /= (den.y + 1e-16f);
            p.z /= (den.z + 1e-16f); p.w /= (den.w + 1e-16f);
            aSh[tid] = p;
        }
        __syncthreads();
        for (int j = 0; j < nE; j++) {
            float a = comp4(aSh[j], h);
            int s = srcSh[j], e = eidSh[j];
            ax += a * __ldg(&d_u1[s * 64 + c]);
            ae += a * __ldg(&ea[(size_t)e * 64 + c]);
            if (c == 0) acct[h * 22 + etSh[j]] += a;
        }
        __syncthreads();
    } else if (nE > 0) {
        float4 sd = ((const float4*)d_sdst)[n];
        float4 mx = make_float4(-1e30f, -1e30f, -1e30f, -1e30f);
        for (int i = beg + tid; i < end; i += 256) {
            float4 l = logit4(ssrc4[d_srcS[i]], sd, se4[d_eid[i]]);
            mx.x = fmaxf(mx.x, l.x); mx.y = fmaxf(mx.y, l.y);
            mx.z = fmaxf(mx.z, l.z); mx.w = fmaxf(mx.w, l.w);
        }
        float4 m = blockMax4(mx, sh8, tid);
        float4 sm = make_float4(0, 0, 0, 0);
        for (int i = beg + tid; i < end; i += 256) {
            float4 l = logit4(ssrc4[d_srcS[i]], sd, se4[d_eid[i]]);
            sm.x += __expf(l.x - m.x); sm.y += __expf(l.y - m.y);
            sm.z += __expf(l.z - m.z); sm.w += __expf(l.w - m.w);
        }
        float4 den = blockSum4(sm, sh8, tid);
        float4 rdn;
        rdn.x = 1.f / (den.x + 1e-16f); rdn.y = 1.f / (den.y + 1e-16f);
        rdn.z = 1.f / (den.z + 1e-16f); rdn.w = 1.f / (den.w + 1e-16f);
        for (int c0 = beg; c0 < end; c0 += 256) {
            int nc = min(256, end - c0);
            if (tid < nc) {
                int i = c0 + tid, s = d_srcS[i], e = d_eid[i];
                srcSh[tid] = s; eidSh[tid] = e; etSh[tid] = d_etS[i];
                float4 l = logit4(ssrc4[s], sd, se4[e]);
                float4 al;
                al.x = __expf(l.x - m.x) * rdn.x; al.y = __expf(l.y - m.y) * rdn.y;
                al.z = __expf(l.z - m.z) * rdn.z; al.w = __expf(l.w - m.w) * rdn.w;
                aSh[tid] = al;
            }
            __syncthreads();
            for (int j = 0; j < nc; j++) {
                float a = comp4(aSh[j], h);
                int s = srcSh[j], e = eidSh[j];
                ax += a * __ldg(&d_u1[s * 64 + c]);
                ae += a * __ldg(&ea[(size_t)e * 64 + c]);
                if (c == 0) acct[h * 22 + etSh[j]] += a;
            }
            __syncthreads();
        }
    } else {
        __syncthreads();
    }
    float* v = &d_v1[(size_t)n * LDA1];
    v[h * K1H + c] = ax;
    v[h * K1H + 64 + c] = ae;
    v[h * K1H + 150 + c] = x[n * 64 + c];
    if (tid < 88) { int hh = tid / 22, t2 = tid % 22; v[hh * K1H + 128 + t2] = acct[tid]; }
    if (tid < 8) v[(tid >> 1) * K1H + 214 + (tid & 1)] = 0.f;
}

// ---------------- K6: nscore layer 2 ----------------
__global__ void k_ns2(const float* __restrict__ nte2) {
    int gw = (blockIdx.x * blockDim.x + threadIdx.x) >> 5;
    if (gw < Nn) nscore_one(gw, threadIdx.x & 31, d_h1, nte2, 256, d_wsrc2, d_wdst2, d_u2);
}

// ---------------- K7: layer-2 attention ----------------
__global__ void k_attn2(const float* __restrict__ ea) {
    int n = blockIdx.x, tid = threadIdx.x;
    __shared__ float4 sh8[8];
    __shared__ float4 aSh[256];
    __shared__ int srcSh[256], eidSh[256], etSh[256];
    __shared__ float acct[88];
    if (tid < 88) acct[tid] = 0.f;
    int beg = d_off[n], end = d_off[n + 1], nE = end - beg;
    int h = tid >> 6, c = tid & 63;
    float ax0 = 0.f, ax1 = 0.f, ax2 = 0.f, ax3 = 0.f, ae = 0.f;
    const float4* ssrc4 = (const float4*)d_ssrc;
    const float4* se4 = (const float4*)d_se2;
    if (nE > 0 && nE <= 256) {
        float4 sd = ((const float4*)d_sdst)[n];
        float4 l = make_float4(-1e30f, -1e30f, -1e30f, -1e30f);
        if (tid < nE) {
            int i = beg + tid, s = d_srcS[i], e = d_eid[i];
            srcSh[tid] = s; eidSh[tid] = e; etSh[tid] = d_etS[i];
            l = logit4(ssrc4[s], sd, se4[e]);
        }
        float4 m = blockMax4(l, sh8, tid);
        float4 p = make_float4(0, 0, 0, 0);
        if (tid < nE) {
            p.x = __expf(l.x - m.x); p.y = __expf(l.y - m.y);
            p.z = __expf(l.z - m.z); p.w = __expf(l.w - m.w);
        }
        float4 den = blockSum4(p, sh8, tid);
        if (tid < nE) {
            p.x /= (den.x + 1e-16f); p.y /= (den.y + 1e-16f);
            p.z /= (den.z + 1e-16f); p.w /= (den.w + 1e-16f);
            aSh[tid] = p;
        }
        __syncthreads();
        for (int j = 0; j < nE; j++) {
            float4 al = aSh[j];
            int s = srcSh[j], e = eidSh[j];
            float u = __ldg(&d_u2[s * 256 + tid]);
            ax0 += al.x * u; ax1 += al.y * u; ax2 += al.z * u; ax3 += al.w * u;
            float a = comp4(al, h);
            ae += a * __ldg(&ea[(size_t)e * 64 + c]);
            if (c == 0) acct[h * 22 + etSh[j]] += a;
        }
        __syncthreads();
    } else if (nE > 0) {
        float4 sd = ((const float4*)d_sdst)[n];
        float4 mx = make_float4(-1e30f, -1e30f, -1e30f, -1e30f);
        for (int i = beg + tid; i < end; i += 256) {
            float4 l = logit4(ssrc4[d_srcS[i]], sd, se4[d_eid[i]]);
            mx.x = fmaxf(mx.x, l.x); mx.y = fmaxf(mx.y, l.y);
            mx.z = fmaxf(mx.z, l.z); mx.w = fmaxf(mx.w, l.w);
        }
        float4 m = blockMax4(mx, sh8, tid);
        float4 sm = make_float4(0, 0, 0, 0);
        for (int i = beg + tid; i < end; i += 256) {
            float4 l = logit4(ssrc4[d_srcS[i]], sd, se4[d_eid[i]]);
            sm.x += __expf(l.x - m.x); sm.y += __expf(l.y - m.y);
            sm.z += __expf(l.z - m.z); sm.w += __expf(l.w - m.w);
        }
        float4 den = blockSum4(sm, sh8, tid);
        float4 rdn;
        rdn.x = 1.f / (den.x + 1e-16f); rdn.y = 1.f / (den.y + 1e-16f);
        rdn.z = 1.f / (den.z + 1e-16f); rdn.w = 1.f / (den.w + 1e-16f);
        for (int c0 = beg; c0 < end; c0 += 256) {
            int nc = min(256, end - c0);
            if (tid < nc) {
                int i = c0 + tid, s = d_srcS[i], e = d_eid[i];
                srcSh[tid] = s; eidSh[tid] = e; etSh[tid] = d_etS[i];
                float4 l = logit4(ssrc4[s], sd, se4[e]);
                float4 al;
                al.x = __expf(l.x - m.x) * rdn.x; al.y = __expf(l.y - m.y) * rdn.y;
                al.z = __expf(l.z - m.z) * rdn.z; al.w = __expf(l.w - m.w) * rdn.w;
                aSh[tid] = al;
            }
            __syncthreads();
            for (int j = 0; j < nc; j++) {
                float4 al = aSh[j];
                int s = srcSh[j], e = eidSh[j];
                float u = __ldg(&d_u2[s * 256 + tid]);
                ax0 += al.x * u; ax1 += al.y * u; ax2 += al.z * u; ax3 += al.w * u;
                float a = comp4(al, h);
                ae += a * __ldg(&ea[(size_t)e * 64 + c]);
                if (c == 0) acct[h * 22 + etSh[j]] += a;
            }
            __syncthreads();
        }
    } else {
        __syncthreads();
    }
    float* v = &d_v2[(size_t)n * K2P];
    v[tid] = ax0; v[256 + tid] = ax1; v[512 + tid] = ax2; v[768 + tid] = ax3;
    v[1024 + tid] = ae;
    if (tid < 88) v[1280 + tid] = acct[tid];
    else if (tid < 96) v[1280 + tid] = 0.f;
}

// ---------------- f32x2 packed SGEMM (unchanged from R4) ----------------
template <int K, int MODE>
__global__ void k_gemmT(const float* __restrict__ A, const float* __restrict__ B,
                        const float* __restrict__ bias, const float* __restrict__ add,
                        float* __restrict__ C) {
    constexpr int LDA = (MODE == 1) ? LDA1 : K2P;
    __shared__ float As[8][132];
    __shared__ float Bs[8][64];
    int y = blockIdx.y;
    int bm = blockIdx.x * 128;
    int colbase = y * 64;
    const float* Ab = A + ((MODE == 1) ? y * K1H : 0);
    const float* Bb = (MODE == 1) ? (B + y * K1H * 64) : (B + colbase);
    const int ldb = (MODE == 1) ? 64 : 256;
    int tid = threadIdx.x;
    int tx = tid & 15, ty = tid >> 4;
    int lrow = tid >> 1, lk = (tid & 1) * 4;
    int brow = tid >> 4, bcol = (tid & 15) * 4;
    unsigned long long acc[4][4];
#pragma unroll
    for (int p = 0; p < 4; p++)
#pragma unroll
        for (int j = 0; j < 4; j++) acc[p][j] = 0ull;
    for (int k0 = 0; k0 < K; k0 += 8) {
        float4 av = make_float4(0, 0, 0, 0);
        int row = bm + lrow;
        if (row < Nn) av = *(const float4*)&Ab[(size_t)row * LDA + k0 + lk];
        As[lk + 0][lrow] = av.x; As[lk + 1][lrow] = av.y;
        As[lk + 2][lrow] = av.z; As[lk + 3][lrow] = av.w;
        if (tid < 128) {
            float4 bv = *(const float4*)&Bb[(size_t)(k0 + brow) * ldb + bcol];
            *(float4*)&Bs[brow][bcol] = bv;
        }
        __syncthreads();
#pragma unroll
        for (int kk = 0; kk < 8; kk++) {
            ulonglong2 a01 = *(const ulonglong2*)&As[kk][ty * 8];
            ulonglong2 a23 = *(const ulonglong2*)&As[kk][ty * 8 + 4];
            float4 bv = *(const float4*)&Bs[kk][tx * 4];
            unsigned long long ap[4] = {a01.x, a01.y, a23.x, a23.y};
            unsigned long long bd[4] = {dup2(bv.x), dup2(bv.y), dup2(bv.z), dup2(bv.w)};
#pragma unroll
            for (int p = 0; p < 4; p++)
#pragma unroll
                for (int j = 0; j < 4; j++) fma2(acc[p][j], ap[p], bd[j]);
        }
        __syncthreads();
    }
#pragma unroll
    for (int p = 0; p < 4; p++) {
        int r0 = bm + ty * 8 + 2 * p;
#pragma unroll
        for (int j = 0; j < 4; j++) {
            int col = colbase + tx * 4 + j;
            float lo = __uint_as_float((unsigned)(acc[p][j] & 0xffffffffull));
            float hi = __uint_as_float((unsigned)(acc[p][j] >> 32));
            float bsv = bias[col];
            if (r0 < Nn) {
                float v = lo + bsv;
                if (MODE == 1) v = fmaxf(v, 0.f);
                else v += add[r0 * 256 + col];
                C[r0 * 256 + col] = v;
            }
            if (r0 + 1 < Nn) {
                float v = hi + bsv;
                if (MODE == 1) v = fmaxf(v, 0.f);
                else v += add[(r0 + 1) * 256 + col];
                C[(r0 + 1) * 256 + col] = v;
            }
        }
    }
}

// ---------------- launch (8 kernels; my #4 = k_attn1 gets profiled) ----------
extern "C" void kernel_launch(void* const* d_in, const int* in_sizes, int n_in,
                              void* d_out, int out_size) {
    const float* x    = (const float*)d_in[0];
    const void*  ei   = d_in[1];
    const void*  ntp  = d_in[2];
    const float* ea   = (const float*)d_in[3];
    const void*  etp  = d_in[4];
    const float* W1   = (const float*)d_in[5];
    const float* b1   = (const float*)d_in[6];
    const float* We1  = (const float*)d_in[7];
    const float* nte1 = (const float*)d_in[8];
    const float* ete1 = (const float*)d_in[9];
    const float* as1  = (const float*)d_in[10];
    const float* ad1  = (const float*)d_in[11];
    const float* ag1  = (const float*)d_in[12];
    const float* res1 = (const float*)d_in[13];
    const float* W2   = (const float*)d_in[14];
    const float* b2   = (const float*)d_in[15];
    const float* We2  = (const float*)d_in[16];
    const float* nte2 = (const float*)d_in[17];
    const float* ete2 = (const float*)d_in[18];
    const float* as2  = (const float*)d_in[19];
    const float* ad2  = (const float*)d_in[20];
    const float* ag2  = (const float*)d_in[21];
    float* out = (float*)d_out;

    k_pre<<<PRE_TOT, 256>>>(ei, ntp, etp, W1, as1, ad1, We1, ag1, ete1,
                            W2, as2, ad2, We2, ag2, ete2, res1);
    k_scan<<<1, 1024>>>();
    k_mid<<<MID_TOT, 256>>>(ea, x, nte1);
    k_attn1<<<Nn, 256>>>(ea, x);

    float* h1;  cudaGetSymbolAddress((void**)&h1, d_h1);
    float* v1;  cudaGetSymbolAddress((void**)&v1, d_v1);
    float* w1h; cudaGetSymbolAddress((void**)&w1h, d_W1h);
    float* v2;  cudaGetSymbolAddress((void**)&v2, d_v2);
    float* w2c; cudaGetSymbolAddress((void**)&w2c, d_W2cat);
    dim3 g((Nn + 127) / 128, 4);
    k_gemmT<K1H, 1><<<g, 256>>>(v1, w1h, b1, nullptr, h1);
    k_ns2<<<(Nn * 32 + 255) / 256, 256>>>(nte2);
    k_attn2<<<Nn, 256>>>(ea);
    k_gemmT<K2P, 2><<<g, 256>>>(v2, w2c, b2, h1, out);
}

// round 6
// speedup vs baseline: 1.2780x; 1.2780x over previous
#include <cuda_runtime.h>
#include <math.h>

#define Nn 10000
#define Ee 320000
#define K1H 216          // per-head K for layer-1 GEMM
#define LDA1 (4 * K1H)   // 864
#define K2P 1376

// ---------------- static scratch ----------------
__device__ int   d_src[Ee], d_dst[Ee], d_et[Ee], d_nt[Nn];
__device__ int   d_deg[Nn], d_off[Nn + 1], d_cur[Nn];
__device__ int   d_eid[Ee], d_srcS[Ee], d_etS[Ee];
__device__ float d_se1[Ee * 4], d_se2[Ee * 4];
__device__ float d_ssrc[Nn * 4], d_sdst[Nn * 4];
__device__ float d_u1[Nn * 64], d_u2[Nn * 256], d_h1[Nn * 256];
__device__ float d_v1[(size_t)Nn * LDA1], d_v2[(size_t)Nn * K2P];
__device__ float d_wsrc1[256], d_wdst1[256], d_wae1[256], d_etd1[22 * 4];
__device__ float d_wsrc2[1024], d_wdst2[1024], d_wae2[256], d_etd2[22 * 4];
__device__ float d_W1h[4 * K1H * 64], d_W2cat[K2P * 256];

typedef unsigned long long ull;

__device__ __forceinline__ float lrelu(float v) { return v > 0.f ? v : 0.2f * v; }
__device__ __forceinline__ int ldidx(const void* p, long long i, int is64) {
    return is64 ? (int)((const long long*)p)[i] : ((const int*)p)[i];
}
__device__ __forceinline__ ull dup2(float x) {
    ull r;
    asm("mov.b64 %0, {%1, %1};" : "=l"(r) : "r"(__float_as_uint(x)));
    return r;
}
__device__ __forceinline__ void fma2(ull& d, ull a, ull b) {
    asm("fma.rn.f32x2 %0, %1, %2, %0;" : "+l"(d) : "l"(a), "l"(b));
}
__device__ __forceinline__ float4 logit4(float4 ss, float4 sd, float4 se) {
    float4 l;
    l.x = lrelu(ss.x + sd.x + se.x); l.y = lrelu(ss.y + sd.y + se.y);
    l.z = lrelu(ss.z + sd.z + se.z); l.w = lrelu(ss.w + sd.w + se.w);
    return l;
}
__device__ __forceinline__ float4 warpMax4(float4 v) {
#pragma unroll
    for (int o = 16; o > 0; o >>= 1) {
        v.x = fmaxf(v.x, __shfl_xor_sync(0xffffffffu, v.x, o));
        v.y = fmaxf(v.y, __shfl_xor_sync(0xffffffffu, v.y, o));
        v.z = fmaxf(v.z, __shfl_xor_sync(0xffffffffu, v.z, o));
        v.w = fmaxf(v.w, __shfl_xor_sync(0xffffffffu, v.w, o));
    }
    return v;
}
__device__ __forceinline__ float4 warpSum4(float4 v) {
#pragma unroll
    for (int o = 16; o > 0; o >>= 1) {
        v.x += __shfl_xor_sync(0xffffffffu, v.x, o);
        v.y += __shfl_xor_sync(0xffffffffu, v.y, o);
        v.z += __shfl_xor_sync(0xffffffffu, v.z, o);
        v.w += __shfl_xor_sync(0xffffffffu, v.w, o);
    }
    return v;
}

// per-block int64 detection from node_type buffer
__device__ __forceinline__ int block_is64(const unsigned int* w) {
    int t = threadIdx.x;
    int bad = 0;
    if (t < 128) bad = (w[2 * (t * 39) + 1] != 0u);
    return __syncthreads_or(bad) ? 0 : 1;
}

// ---------------- K1: fused preprocessing ----------------
#define PRE_CONV 1250
#define PRE_PW1  (PRE_CONV + 216)
#define PRE_PW2  (PRE_PW1 + 1376)
#define PRE_TOT  (PRE_PW2 + 13)

__global__ void k_pre(const void* ei, const void* ntp, const void* etp,
                      const float* W1, const float* as1, const float* ad1,
                      const float* We1, const float* ag1, const float* etb1,
                      const float* W2, const float* as2, const float* ad2,
                      const float* We2, const float* ag2, const float* etb2,
                      const float* res1) {
    int b = blockIdx.x, t = threadIdx.x;
    if (b < PRE_CONV) {
        int is64 = block_is64((const unsigned int*)ntp);
        int e = b * 256 + t;
        if (e < Ee) {
            int s = ldidx(ei, e, is64);
            int d2 = ldidx(ei, (long long)Ee + e, is64);
            d_src[e] = s; d_dst[e] = d2; d_et[e] = ldidx(etp, e, is64);
            atomicAdd(&d_deg[d2], 1);
        }
        if (b < 40) { int i = b * 256 + t; if (i < Nn) d_nt[i] = ldidx(ntp, i, is64); }
    } else if (b < PRE_PW1) {
        int j = (b - PRE_CONV) * 256 + t;
        int c = j & 63, hk = j >> 6, h = hk / K1H, k = hk - h * K1H;
        float v = 0.f;
        if (k < 64) v = W1[k * 256 + h * 64 + c];
        else if (k < 128) v = We1[(k - 64) * 256 + h * 64 + c];
        else if (k < 150) v = etb1[(k - 128) * 256 + h * 64 + c];
        else if (k < 214) v = res1[(k - 150) * 256 + h * 64 + c];
        d_W1h[j] = v;
    } else if (b < PRE_PW2) {
        int j = (b - PRE_PW1) * 256 + t;
        int col = j & 255, r = j >> 8;
        float v = 0.f;
        if (r < 1024) { int h = r >> 8, k = r & 255; v = W2[k * 1024 + h * 256 + col] * 0.25f; }
        else if (r < 1280) { int rr = r - 1024, h = rr >> 6, k = rr & 63; v = We2[k * 1024 + h * 256 + col] * 0.25f; }
        else if (r < 1368) { int rr = r - 1280, h = rr / 22, tt = rr % 22; v = etb2[tt * 1024 + h * 256 + col] * 0.25f; }
        d_W2cat[j] = v;
    } else {
        int j = (b - PRE_PW2) * 256 + t;
        if (j < 256) {
            int h = j >> 6, k = j & 63; float s = 0.f;
            for (int c = 0; c < 64; c++) s += W1[k * 256 + h * 64 + c] * as1[h * 64 + c];
            d_wsrc1[j] = s;
        } else if (j < 512) {
            int jj = j - 256, h = jj >> 6, k = jj & 63; float s = 0.f;
            for (int c = 0; c < 64; c++) s += W1[k * 256 + h * 64 + c] * ad1[h * 64 + c];
            d_wdst1[jj] = s;
        } else if (j < 768) {
            int jj = j - 512, h = jj >> 6, k = jj & 63; float s = 0.f;
            for (int c = 0; c < 64; c++) s += We1[k * 256 + h * 64 + c] * ag1[h * 64 + c];
            d_wae1[jj] = s;
        } else if (j < 856) {
            int jj = j - 768, tt = jj >> 2, h = jj & 3; float s = 0.f;
            for (int c = 0; c < 64; c++) s += etb1[tt * 256 + h * 64 + c] * ag1[h * 64 + c];
            d_etd1[jj] = s;
        } else if (j < 1880) {
            int jj = j - 856, h = jj >> 8, k = jj & 255; float s = 0.f;
            for (int c = 0; c < 256; c++) s += W2[k * 1024 + h * 256 + c] * as2[h * 256 + c];
            d_wsrc2[jj] = s;
        } else if (j < 2904) {
            int jj = j - 1880, h = jj >> 8, k = jj & 255; float s = 0.f;
            for (int c = 0; c < 256; c++) s += W2[k * 1024 + h * 256 + c] * ad2[h * 256 + c];
            d_wdst2[jj] = s;
        } else if (j < 3160) {
            int jj = j - 2904, h = jj >> 6, k = jj & 63; float s = 0.f;
            for (int c = 0; c < 256; c++) s += We2[k * 1024 + h * 256 + c] * ag2[h * 256 + c];
            d_wae2[jj] = s;
        } else if (j < 3248) {
            int jj = j - 3160, tt = jj >> 2, h = jj & 3; float s = 0.f;
            for (int c = 0; c < 256; c++) s += etb2[tt * 1024 + h * 256 + c] * ag2[h * 256 + c];
            d_etd2[jj] = s;
        }
    }
}

// ---------------- K2: scan (+ zero d_deg for replay) ----------------
__global__ void k_scan() {
    __shared__ int wsum[32];
    int t = threadIdx.x, base = t * 10, loc[10], sum = 0;
#pragma unroll
    for (int ii = 0; ii < 10; ii++) {
        int i = base + ii;
        int d = (i < Nn) ? d_deg[i] : 0;
        loc[ii] = d; sum += d;
    }
    int lane = t & 31, w = t >> 5;
    int v = sum;
#pragma unroll
    for (int o = 1; o < 32; o <<= 1) {
        int u = __shfl_up_sync(0xffffffffu, v, o);
        if (lane >= o) v += u;
    }
    if (lane == 31) wsum[w] = v;
    __syncthreads();
    if (w == 0) {
        int s = wsum[lane];
#pragma unroll
        for (int o = 1; o < 32; o <<= 1) {
            int u = __shfl_up_sync(0xffffffffu, s, o);
            if (lane >= o) s += u;
        }
        wsum[lane] = s;
    }
    __syncthreads();
    int run = v - sum + (w ? wsum[w - 1] : 0);
#pragma unroll
    for (int ii = 0; ii < 10; ii++) {
        int i = base + ii;
        if (i < Nn) { d_off[i] = run; d_cur[i] = run; d_deg[i] = 0; run += loc[ii]; }
        else if (i == Nn) d_off[Nn] = run;
    }
}

// ---------------- nscore body ----------------
__device__ __forceinline__ void nscore_one(int gw, int lane, const float* xin,
                                           const float* ntemb, int K,
                                           const float* ws, const float* wd, float* u) {
    int nt = d_nt[gw];
    float ps[4] = {0, 0, 0, 0}, pd[4] = {0, 0, 0, 0};
    for (int k = lane; k < K; k += 32) {
        float v = xin[gw * K + k] + ntemb[nt * K + k];
        u[gw * K + k] = v;
#pragma unroll
        for (int h = 0; h < 4; h++) { ps[h] += v * ws[h * K + k]; pd[h] += v * wd[h * K + k]; }
    }
#pragma unroll
    for (int h = 0; h < 4; h++)
        for (int o = 16; o > 0; o >>= 1) {
            ps[h] += __shfl_xor_sync(0xffffffffu, ps[h], o);
            pd[h] += __shfl_xor_sync(0xffffffffu, pd[h], o);
        }
    if (lane == 0)
#pragma unroll
        for (int h = 0; h < 4; h++) { d_ssrc[gw * 4 + h] = ps[h]; d_sdst[gw * 4 + h] = pd[h]; }
}

// ---------------- K3: fused scatter + nscore1 + edgescore ----------------
#define MID_SCAT 1250
#define MID_NS   (MID_SCAT + 1250)
#define MID_TOT  (MID_NS + 40000)

__global__ void k_mid(const float* __restrict__ ea, const float* __restrict__ x,
                      const float* __restrict__ nte1) {
    int b = blockIdx.x, t = threadIdx.x;
    if (b < MID_SCAT) {
        int e = b * 256 + t;
        if (e < Ee) {
            int p = atomicAdd(&d_cur[d_dst[e]], 1);
            d_eid[p] = e; d_srcS[p] = d_src[e]; d_etS[p] = d_et[e];
        }
    } else if (b < MID_NS) {
        int gw = (b - MID_SCAT) * 8 + (t >> 5);
        if (gw < Nn) nscore_one(gw, t & 31, x, nte1, 64, d_wsrc1, d_wdst1, d_u1);
    } else {
        int e = (b - MID_NS) * 8 + (t >> 5);
        int lane = t & 31;
        float a0 = ea[(size_t)e * 64 + lane];
        float a1 = ea[(size_t)e * 64 + 32 + lane];
        float dd1[4], dd2[4];
#pragma unroll
        for (int h = 0; h < 4; h++) {
            dd1[h] = a0 * d_wae1[h * 64 + lane] + a1 * d_wae1[h * 64 + 32 + lane];
            dd2[h] = a0 * d_wae2[h * 64 + lane] + a1 * d_wae2[h * 64 + 32 + lane];
            for (int o = 16; o > 0; o >>= 1) {
                dd1[h] += __shfl_xor_sync(0xffffffffu, dd1[h], o);
                dd2[h] += __shfl_xor_sync(0xffffffffu, dd2[h], o);
            }
        }
        if (lane == 0) {
            int et = d_et[e];
#pragma unroll
            for (int h = 0; h < 4; h++) {
                d_se1[e * 4 + h] = dd1[h] + d_etd1[et * 4 + h];
                d_se2[e * 4 + h] = dd2[h] + d_etd2[et * 4 + h];
            }
        }
    }
}

// ---- shared softmax-alpha machinery for warp-per-node attention ----
// computes m, rdn for node n's edge range via warp ops
__device__ __forceinline__ void warp_softmax(const float4* se4, int beg, int end,
                                             int lane, float4 sd, float4& m, float4& rdn) {
    const float4* ssrc4 = (const float4*)d_ssrc;
    float4 mx = make_float4(-1e30f, -1e30f, -1e30f, -1e30f);
    for (int i = beg + lane; i < end; i += 32) {
        float4 l = logit4(ssrc4[d_srcS[i]], sd, se4[d_eid[i]]);
        mx.x = fmaxf(mx.x, l.x); mx.y = fmaxf(mx.y, l.y);
        mx.z = fmaxf(mx.z, l.z); mx.w = fmaxf(mx.w, l.w);
    }
    m = warpMax4(mx);
    float4 sm = make_float4(0, 0, 0, 0);
    for (int i = beg + lane; i < end; i += 32) {
        float4 l = logit4(ssrc4[d_srcS[i]], sd, se4[d_eid[i]]);
        sm.x += __expf(l.x - m.x); sm.y += __expf(l.y - m.y);
        sm.z += __expf(l.z - m.z); sm.w += __expf(l.w - m.w);
    }
    float4 den = warpSum4(sm);
    rdn.x = 1.f / (den.x + 1e-16f); rdn.y = 1.f / (den.y + 1e-16f);
    rdn.z = 1.f / (den.z + 1e-16f); rdn.w = 1.f / (den.w + 1e-16f);
}

// ---------------- K4: warp-per-node layer-1 attention ----------------
__global__ void k_attn1(const float* __restrict__ ea, const float* __restrict__ x) {
    int wid = threadIdx.x >> 5, lane = threadIdx.x & 31;
    int n = blockIdx.x * 8 + wid;
    __shared__ float acctSh[8][88];
    for (int i = lane; i < 88; i += 32) acctSh[wid][i] = 0.f;
    __syncwarp();
    int beg = d_off[n], end = d_off[n + 1], nE = end - beg;
    ull ax[4] = {0, 0, 0, 0}, av[4] = {0, 0, 0, 0};
    if (nE > 0) {
        const float4* ssrc4 = (const float4*)d_ssrc;
        const float4* se4 = (const float4*)d_se1;
        float4 sd = ((const float4*)d_sdst)[n];
        float4 m, rdn;
        warp_softmax(se4, beg, end, lane, sd, m, rdn);
        for (int c0 = beg; c0 < end; c0 += 32) {
            int nc = min(32, end - c0);
            float al0 = 0.f, al1 = 0.f, al2 = 0.f, al3 = 0.f;
            int sj = 0, ej = 0, etj = 0;
            if (lane < nc) {
                int i = c0 + lane;
                sj = d_srcS[i]; ej = d_eid[i]; etj = d_etS[i];
                float4 l = logit4(ssrc4[sj], sd, se4[ej]);
                al0 = __expf(l.x - m.x) * rdn.x; al1 = __expf(l.y - m.y) * rdn.y;
                al2 = __expf(l.z - m.z) * rdn.z; al3 = __expf(l.w - m.w) * rdn.w;
            }
            for (int j = 0; j < nc; j++) {
                float a0 = __shfl_sync(0xffffffffu, al0, j);
                float a1 = __shfl_sync(0xffffffffu, al1, j);
                float a2 = __shfl_sync(0xffffffffu, al2, j);
                float a3 = __shfl_sync(0xffffffffu, al3, j);
                int s = __shfl_sync(0xffffffffu, sj, j);
                int e = __shfl_sync(0xffffffffu, ej, j);
                int et = __shfl_sync(0xffffffffu, etj, j);
                ull u = *(const ull*)&d_u1[s * 64 + lane * 2];
                ull a = *(const ull*)&ea[(size_t)e * 64 + lane * 2];
                fma2(ax[0], u, dup2(a0)); fma2(ax[1], u, dup2(a1));
                fma2(ax[2], u, dup2(a2)); fma2(ax[3], u, dup2(a3));
                fma2(av[0], a, dup2(a0)); fma2(av[1], a, dup2(a1));
                fma2(av[2], a, dup2(a2)); fma2(av[3], a, dup2(a3));
                if (lane < 4) {
                    float aa = lane == 0 ? a0 : (lane == 1 ? a1 : (lane == 2 ? a2 : a3));
                    acctSh[wid][lane * 22 + et] += aa;
                }
            }
        }
    }
    __syncwarp();
    float* v = &d_v1[(size_t)n * LDA1];
    int c = lane * 2;
#pragma unroll
    for (int h = 0; h < 4; h++) {
        *(ull*)&v[h * K1H + c] = ax[h];
        *(ull*)&v[h * K1H + 64 + c] = av[h];
        *(ull*)&v[h * K1H + 150 + c] = *(const ull*)&x[n * 64 + c];
    }
    for (int i = lane; i < 88; i += 32) {
        int hh = i / 22, t2 = i % 22;
        v[hh * K1H + 128 + t2] = acctSh[wid][i];
    }
    if (lane < 8) v[(lane >> 1) * K1H + 214 + (lane & 1)] = 0.f;
}

// ---------------- K6: nscore layer 2 ----------------
__global__ void k_ns2(const float* __restrict__ nte2) {
    int gw = (blockIdx.x * blockDim.x + threadIdx.x) >> 5;
    if (gw < Nn) nscore_one(gw, threadIdx.x & 31, d_h1, nte2, 256, d_wsrc2, d_wdst2, d_u2);
}

// ---------------- K7: warp-per-node layer-2 attention ----------------
__global__ void k_attn2(const float* __restrict__ ea) {
    int wid = threadIdx.x >> 5, lane = threadIdx.x & 31;
    int n = blockIdx.x * 8 + wid;
    __shared__ float acctSh[8][88];
    for (int i = lane; i < 88; i += 32) acctSh[wid][i] = 0.f;
    __syncwarp();
    int beg = d_off[n], end = d_off[n + 1], nE = end - beg;
    ull axu[4][4];
#pragma unroll
    for (int h = 0; h < 4; h++)
#pragma unroll
        for (int q = 0; q < 4; q++) axu[h][q] = 0ull;
    ull av[4] = {0, 0, 0, 0};
    if (nE > 0) {
        const float4* ssrc4 = (const float4*)d_ssrc;
        const float4* se4 = (const float4*)d_se2;
        float4 sd = ((const float4*)d_sdst)[n];
        float4 m, rdn;
        warp_softmax(se4, beg, end, lane, sd, m, rdn);
        for (int c0 = beg; c0 < end; c0 += 32) {
            int nc = min(32, end - c0);
            float al0 = 0.f, al1 = 0.f, al2 = 0.f, al3 = 0.f;
            int sj = 0, ej = 0, etj = 0;
            if (lane < nc) {
                int i = c0 + lane;
                sj = d_srcS[i]; ej = d_eid[i]; etj = d_etS[i];
                float4 l = logit4(ssrc4[sj], sd, se4[ej]);
                al0 = __expf(l.x - m.x) * rdn.x; al1 = __expf(l.y - m.y) * rdn.y;
                al2 = __expf(l.z - m.z) * rdn.z; al3 = __expf(l.w - m.w) * rdn.w;
            }
            for (int j = 0; j < nc; j++) {
                float a0 = __shfl_sync(0xffffffffu, al0, j);
                float a1 = __shfl_sync(0xffffffffu, al1, j);
                float a2 = __shfl_sync(0xffffffffu, al2, j);
                float a3 = __shfl_sync(0xffffffffu, al3, j);
                int s = __shfl_sync(0xffffffffu, sj, j);
                int e = __shfl_sync(0xffffffffu, ej, j);
                int et = __shfl_sync(0xffffffffu, etj, j);
                const float4* up = (const float4*)&d_u2[s * 256 + lane * 8];
                float4 u0 = up[0], u1 = up[1];
                ull p0 = *(ull*)&u0.x, p1 = *(ull*)&u0.z;
                ull p2 = *(ull*)&u1.x, p3 = *(ull*)&u1.z;
                ull da0 = dup2(a0), da1 = dup2(a1), da2 = dup2(a2), da3 = dup2(a3);
                fma2(axu[0][0], p0, da0); fma2(axu[0][1], p1, da0);
                fma2(axu[0][2], p2, da0); fma2(axu[0][3], p3, da0);
                fma2(axu[1][0], p0, da1); fma2(axu[1][1], p1, da1);
                fma2(axu[1][2], p2, da1); fma2(axu[1][3], p3, da1);
                fma2(axu[2][0], p0, da2); fma2(axu[2][1], p1, da2);
                fma2(axu[2][2], p2, da2); fma2(axu[2][3], p3, da2);
                fma2(axu[3][0], p0, da3); fma2(axu[3][1], p1, da3);
                fma2(axu[3][2], p2, da3); fma2(axu[3][3], p3, da3);
                ull a = *(const ull*)&ea[(size_t)e * 64 + lane * 2];
                fma2(av[0], a, da0); fma2(av[1], a, da1);
                fma2(av[2], a, da2); fma2(av[3], a, da3);
                if (lane < 4) {
                    float aa = lane == 0 ? a0 : (lane == 1 ? a1 : (lane == 2 ? a2 : a3));
                    acctSh[wid][lane * 22 + et] += aa;
                }
            }
        }
    }
    __syncwarp();
    float* v = &d_v2[(size_t)n * K2P];
#pragma unroll
    for (int h = 0; h < 4; h++) {
#pragma unroll
        for (int q = 0; q < 4; q++)
            *(ull*)&v[h * 256 + lane * 8 + q * 2] = axu[h][q];
        *(ull*)&v[1024 + h * 64 + lane * 2] = av[h];
    }
    for (int i = lane; i < 96; i += 32)
        v[1280 + i] = (i < 88) ? acctSh[wid][i] : 0.f;
}

// ---------------- f32x2 packed SGEMM ----------------
template <int K, int MODE>
__global__ void k_gemmT(const float* __restrict__ A, const float* __restrict__ B,
                        const float* __restrict__ bias, const float* __restrict__ add,
                        float* __restrict__ C) {
    constexpr int LDA = (MODE == 1) ? LDA1 : K2P;
    __shared__ float As[8][132];
    __shared__ float Bs[8][64];
    int y = blockIdx.y;
    int bm = blockIdx.x * 128;
    int colbase = y * 64;
    const float* Ab = A + ((MODE == 1) ? y * K1H : 0);
    const float* Bb = (MODE == 1) ? (B + y * K1H * 64) : (B + colbase);
    const int ldb = (MODE == 1) ? 64 : 256;
    int tid = threadIdx.x;
    int tx = tid & 15, ty = tid >> 4;
    int lrow = tid >> 1, lk = (tid & 1) * 4;
    int brow = tid >> 4, bcol = (tid & 15) * 4;
    ull acc[4][4];
#pragma unroll
    for (int p = 0; p < 4; p++)
#pragma unroll
        for (int j = 0; j < 4; j++) acc[p][j] = 0ull;
    for (int k0 = 0; k0 < K; k0 += 8) {
        float4 avv = make_float4(0, 0, 0, 0);
        int row = bm + lrow;
        if (row < Nn) avv = *(const float4*)&Ab[(size_t)row * LDA + k0 + lk];
        As[lk + 0][lrow] = avv.x; As[lk + 1][lrow] = avv.y;
        As[lk + 2][lrow] = avv.z; As[lk + 3][lrow] = avv.w;
        if (tid < 128) {
            float4 bv = *(const float4*)&Bb[(size_t)(k0 + brow) * ldb + bcol];
            *(float4*)&Bs[brow][bcol] = bv;
        }
        __syncthreads();
#pragma unroll
        for (int kk = 0; kk < 8; kk++) {
            ulonglong2 a01 = *(const ulonglong2*)&As[kk][ty * 8];
            ulonglong2 a23 = *(const ulonglong2*)&As[kk][ty * 8 + 4];
            float4 bv = *(const float4*)&Bs[kk][tx * 4];
            ull ap[4] = {a01.x, a01.y, a23.x, a23.y};
            ull bd[4] = {dup2(bv.x), dup2(bv.y), dup2(bv.z), dup2(bv.w)};
#pragma unroll
            for (int p = 0; p < 4; p++)
#pragma unroll
                for (int j = 0; j < 4; j++) fma2(acc[p][j], ap[p], bd[j]);
        }
        __syncthreads();
    }
#pragma unroll
    for (int p = 0; p < 4; p++) {
        int r0 = bm + ty * 8 + 2 * p;
#pragma unroll
        for (int j = 0; j < 4; j++) {
            int col = colbase + tx * 4 + j;
            float lo = __uint_as_float((unsigned)(acc[p][j] & 0xffffffffull));
            float hi = __uint_as_float((unsigned)(acc[p][j] >> 32));
            float bsv = bias[col];
            if (r0 < Nn) {
                float v = lo + bsv;
                if (MODE == 1) v = fmaxf(v, 0.f);
                else v += add[r0 * 256 + col];
                C[r0 * 256 + col] = v;
            }
            if (r0 + 1 < Nn) {
                float v = hi + bsv;
                if (MODE == 1) v = fmaxf(v, 0.f);
                else v += add[(r0 + 1) * 256 + col];
                C[(r0 + 1) * 256 + col] = v;
            }
        }
    }
}

// ---------------- launch ----------------
extern "C" void kernel_launch(void* const* d_in, const int* in_sizes, int n_in,
                              void* d_out, int out_size) {
    const float* x    = (const float*)d_in[0];
    const void*  ei   = d_in[1];
    const void*  ntp  = d_in[2];
    const float* ea   = (const float*)d_in[3];
    const void*  etp  = d_in[4];
    const float* W1   = (const float*)d_in[5];
    const float* b1   = (const float*)d_in[6];
    const float* We1  = (const float*)d_in[7];
    const float* nte1 = (const float*)d_in[8];
    const float* ete1 = (const float*)d_in[9];
    const float* as1  = (const float*)d_in[10];
    const float* ad1  = (const float*)d_in[11];
    const float* ag1  = (const float*)d_in[12];
    const float* res1 = (const float*)d_in[13];
    const float* W2   = (const float*)d_in[14];
    const float* b2   = (const float*)d_in[15];
    const float* We2  = (const float*)d_in[16];
    const float* nte2 = (const float*)d_in[17];
    const float* ete2 = (const float*)d_in[18];
    const float* as2  = (const float*)d_in[19];
    const float* ad2  = (const float*)d_in[20];
    const float* ag2  = (const float*)d_in[21];
    float* out = (float*)d_out;

    k_pre<<<PRE_TOT, 256>>>(ei, ntp, etp, W1, as1, ad1, We1, ag1, ete1,
                            W2, as2, ad2, We2, ag2, ete2, res1);
    k_scan<<<1, 1024>>>();
    k_mid<<<MID_TOT, 256>>>(ea, x, nte1);
    k_attn1<<<Nn / 8, 256>>>(ea, x);

    float* h1;  cudaGetSymbolAddress((void**)&h1, d_h1);
    float* v1;  cudaGetSymbolAddress((void**)&v1, d_v1);
    float* w1h; cudaGetSymbolAddress((void**)&w1h, d_W1h);
    float* v2;  cudaGetSymbolAddress((void**)&v2, d_v2);
    float* w2c; cudaGetSymbolAddress((void**)&w2c, d_W2cat);
    dim3 g((Nn + 127) / 128, 4);
    k_gemmT<K1H, 1><<<g, 256>>>(v1, w1h, b1, nullptr, h1);
    k_ns2<<<(Nn * 32 + 255) / 256, 256>>>(nte2);
    k_attn2<<<Nn / 8, 256>>>(ea);
    k_gemmT<K2P, 2><<<g, 256>>>(v2, w2c, b2, h1, out);
}

// round 7
// speedup vs baseline: 1.5419x; 1.2065x over previous
#include <cuda_runtime.h>
#include <math.h>

#define Nn 10000
#define Ee 320000
#define K1H 216          // per-head K for layer-1 GEMM
#define LDA1 (4 * K1H)   // 864
#define K2P 1376

// ---------------- static scratch ----------------
__device__ int   d_src[Ee], d_dst[Ee], d_et[Ee], d_nt[Nn];
__device__ int   d_deg[Nn], d_off[Nn + 1], d_cur[Nn];
__device__ int   d_eid[Ee], d_srcS[Ee], d_etS[Ee];
__device__ float d_se1[Ee * 4], d_se2[Ee * 4];
__device__ float d_ssrc[Nn * 4], d_sdst[Nn * 4];
__device__ float d_u1[Nn * 64], d_u2[Nn * 256], d_h1[Nn * 256];
__device__ float d_v1[(size_t)Nn * LDA1], d_v2[(size_t)Nn * K2P];
__device__ float d_wsrc1[256], d_wdst1[256], d_wae1[256], d_etd1[22 * 4];
__device__ float d_wsrc2[1024], d_wdst2[1024], d_wae2[256], d_etd2[22 * 4];
__device__ float d_W1h[4 * K1H * 64], d_W2cat[K2P * 256];

typedef unsigned long long ull;

__device__ __forceinline__ float lrelu(float v) { return v > 0.f ? v : 0.2f * v; }
__device__ __forceinline__ int ldidx(const void* p, long long i, int is64) {
    return is64 ? (int)((const long long*)p)[i] : ((const int*)p)[i];
}
__device__ __forceinline__ ull dup2(float x) {
    ull r;
    asm("mov.b64 %0, {%1, %1};" : "=l"(r) : "r"(__float_as_uint(x)));
    return r;
}
__device__ __forceinline__ void fma2(ull& d, ull a, ull b) {
    asm("fma.rn.f32x2 %0, %1, %2, %0;" : "+l"(d) : "l"(a), "l"(b));
}
__device__ __forceinline__ float4 logit4(float4 ss, float4 sd, float4 se) {
    float4 l;
    l.x = lrelu(ss.x + sd.x + se.x); l.y = lrelu(ss.y + sd.y + se.y);
    l.z = lrelu(ss.z + sd.z + se.z); l.w = lrelu(ss.w + sd.w + se.w);
    return l;
}
__device__ __forceinline__ float4 warpMax4(float4 v) {
#pragma unroll
    for (int o = 16; o > 0; o >>= 1) {
        v.x = fmaxf(v.x, __shfl_xor_sync(0xffffffffu, v.x, o));
        v.y = fmaxf(v.y, __shfl_xor_sync(0xffffffffu, v.y, o));
        v.z = fmaxf(v.z, __shfl_xor_sync(0xffffffffu, v.z, o));
        v.w = fmaxf(v.w, __shfl_xor_sync(0xffffffffu, v.w, o));
    }
    return v;
}
__device__ __forceinline__ float4 warpSum4(float4 v) {
#pragma unroll
    for (int o = 16; o > 0; o >>= 1) {
        v.x += __shfl_xor_sync(0xffffffffu, v.x, o);
        v.y += __shfl_xor_sync(0xffffffffu, v.y, o);
        v.z += __shfl_xor_sync(0xffffffffu, v.z, o);
        v.w += __shfl_xor_sync(0xffffffffu, v.w, o);
    }
    return v;
}

// per-block int64 detection from node_type buffer
__device__ __forceinline__ int block_is64(const unsigned int* w) {
    int t = threadIdx.x;
    int bad = 0;
    if (t < 128) bad = (w[2 * (t * 39) + 1] != 0u);
    return __syncthreads_or(bad) ? 0 : 1;
}

// ---------------- K1: fused preprocessing ----------------
#define PRE_CONV 1250
#define PRE_PW1  (PRE_CONV + 216)
#define PRE_PW2  (PRE_PW1 + 1376)
#define PRE_TOT  (PRE_PW2 + 13)

__global__ void k_pre(const void* ei, const void* ntp, const void* etp,
                      const float* W1, const float* as1, const float* ad1,
                      const float* We1, const float* ag1, const float* etb1,
                      const float* W2, const float* as2, const float* ad2,
                      const float* We2, const float* ag2, const float* etb2,
                      const float* res1) {
    int b = blockIdx.x, t = threadIdx.x;
    if (b < PRE_CONV) {
        int is64 = block_is64((const unsigned int*)ntp);
        int e = b * 256 + t;
        if (e < Ee) {
            int s = ldidx(ei, e, is64);
            int d2 = ldidx(ei, (long long)Ee + e, is64);
            d_src[e] = s; d_dst[e] = d2; d_et[e] = ldidx(etp, e, is64);
            atomicAdd(&d_deg[d2], 1);
        }
        if (b < 40) { int i = b * 256 + t; if (i < Nn) d_nt[i] = ldidx(ntp, i, is64); }
    } else if (b < PRE_PW1) {
        int j = (b - PRE_CONV) * 256 + t;
        int c = j & 63, hk = j >> 6, h = hk / K1H, k = hk - h * K1H;
        float v = 0.f;
        if (k < 64) v = W1[k * 256 + h * 64 + c];
        else if (k < 128) v = We1[(k - 64) * 256 + h * 64 + c];
        else if (k < 150) v = etb1[(k - 128) * 256 + h * 64 + c];
        else if (k < 214) v = res1[(k - 150) * 256 + h * 64 + c];
        d_W1h[j] = v;
    } else if (b < PRE_PW2) {
        int j = (b - PRE_PW1) * 256 + t;
        int col = j & 255, r = j >> 8;
        float v = 0.f;
        if (r < 1024) { int h = r >> 8, k = r & 255; v = W2[k * 1024 + h * 256 + col] * 0.25f; }
        else if (r < 1280) { int rr = r - 1024, h = rr >> 6, k = rr & 63; v = We2[k * 1024 + h * 256 + col] * 0.25f; }
        else if (r < 1368) { int rr = r - 1280, h = rr / 22, tt = rr % 22; v = etb2[tt * 1024 + h * 256 + col] * 0.25f; }
        d_W2cat[j] = v;
    } else {
        int j = (b - PRE_PW2) * 256 + t;
        if (j < 256) {
            int h = j >> 6, k = j & 63; float s = 0.f;
            for (int c = 0; c < 64; c++) s += W1[k * 256 + h * 64 + c] * as1[h * 64 + c];
            d_wsrc1[j] = s;
        } else if (j < 512) {
            int jj = j - 256, h = jj >> 6, k = jj & 63; float s = 0.f;
            for (int c = 0; c < 64; c++) s += W1[k * 256 + h * 64 + c] * ad1[h * 64 + c];
            d_wdst1[jj] = s;
        } else if (j < 768) {
            int jj = j - 512, h = jj >> 6, k = jj & 63; float s = 0.f;
            for (int c = 0; c < 64; c++) s += We1[k * 256 + h * 64 + c] * ag1[h * 64 + c];
            d_wae1[jj] = s;
        } else if (j < 856) {
            int jj = j - 768, tt = jj >> 2, h = jj & 3; float s = 0.f;
            for (int c = 0; c < 64; c++) s += etb1[tt * 256 + h * 64 + c] * ag1[h * 64 + c];
            d_etd1[jj] = s;
        } else if (j < 1880) {
            int jj = j - 856, h = jj >> 8, k = jj & 255; float s = 0.f;
            for (int c = 0; c < 256; c++) s += W2[k * 1024 + h * 256 + c] * as2[h * 256 + c];
            d_wsrc2[jj] = s;
        } else if (j < 2904) {
            int jj = j - 1880, h = jj >> 8, k = jj & 255; float s = 0.f;
            for (int c = 0; c < 256; c++) s += W2[k * 1024 + h * 256 + c] * ad2[h * 256 + c];
            d_wdst2[jj] = s;
        } else if (j < 3160) {
            int jj = j - 2904, h = jj >> 6, k = jj & 63; float s = 0.f;
            for (int c = 0; c < 256; c++) s += We2[k * 1024 + h * 256 + c] * ag2[h * 256 + c];
            d_wae2[jj] = s;
        } else if (j < 3248) {
            int jj = j - 3160, tt = jj >> 2, h = jj & 3; float s = 0.f;
            for (int c = 0; c < 256; c++) s += etb2[tt * 1024 + h * 256 + c] * ag2[h * 256 + c];
            d_etd2[jj] = s;
        }
    }
}

// ---------------- K2: scan (+ zero d_deg for replay) ----------------
__global__ void k_scan() {
    __shared__ int wsum[32];
    int t = threadIdx.x, base = t * 10, loc[10], sum = 0;
#pragma unroll
    for (int ii = 0; ii < 10; ii++) {
        int i = base + ii;
        int d = (i < Nn) ? d_deg[i] : 0;
        loc[ii] = d; sum += d;
    }
    int lane = t & 31, w = t >> 5;
    int v = sum;
#pragma unroll
    for (int o = 1; o < 32; o <<= 1) {
        int u = __shfl_up_sync(0xffffffffu, v, o);
        if (lane >= o) v += u;
    }
    if (lane == 31) wsum[w] = v;
    __syncthreads();
    if (w == 0) {
        int s = wsum[lane];
#pragma unroll
        for (int o = 1; o < 32; o <<= 1) {
            int u = __shfl_up_sync(0xffffffffu, s, o);
            if (lane >= o) s += u;
        }
        wsum[lane] = s;
    }
    __syncthreads();
    int run = v - sum + (w ? wsum[w - 1] : 0);
#pragma unroll
    for (int ii = 0; ii < 10; ii++) {
        int i = base + ii;
        if (i < Nn) { d_off[i] = run; d_cur[i] = run; d_deg[i] = 0; run += loc[ii]; }
        else if (i == Nn) d_off[Nn] = run;
    }
}

// ---------------- nscore body ----------------
__device__ __forceinline__ void nscore_one(int gw, int lane, const float* xin,
                                           const float* ntemb, int K,
                                           const float* ws, const float* wd, float* u) {
    int nt = d_nt[gw];
    float ps[4] = {0, 0, 0, 0}, pd[4] = {0, 0, 0, 0};
    for (int k = lane; k < K; k += 32) {
        float v = xin[gw * K + k] + ntemb[nt * K + k];
        u[gw * K + k] = v;
#pragma unroll
        for (int h = 0; h < 4; h++) { ps[h] += v * ws[h * K + k]; pd[h] += v * wd[h * K + k]; }
    }
#pragma unroll
    for (int h = 0; h < 4; h++)
        for (int o = 16; o > 0; o >>= 1) {
            ps[h] += __shfl_xor_sync(0xffffffffu, ps[h], o);
            pd[h] += __shfl_xor_sync(0xffffffffu, pd[h], o);
        }
    if (lane == 0)
#pragma unroll
        for (int h = 0; h < 4; h++) { d_ssrc[gw * 4 + h] = ps[h]; d_sdst[gw * 4 + h] = pd[h]; }
}

// ---------------- K3: fused scatter + nscore1 + edgescore ----------------
#define MID_SCAT 1250
#define MID_NS   (MID_SCAT + 1250)
#define MID_TOT  (MID_NS + 40000)

__global__ void k_mid(const float* __restrict__ ea, const float* __restrict__ x,
                      const float* __restrict__ nte1) {
    int b = blockIdx.x, t = threadIdx.x;
    if (b < MID_SCAT) {
        int e = b * 256 + t;
        if (e < Ee) {
            int p = atomicAdd(&d_cur[d_dst[e]], 1);
            d_eid[p] = e; d_srcS[p] = d_src[e]; d_etS[p] = d_et[e];
        }
    } else if (b < MID_NS) {
        int gw = (b - MID_SCAT) * 8 + (t >> 5);
        if (gw < Nn) nscore_one(gw, t & 31, x, nte1, 64, d_wsrc1, d_wdst1, d_u1);
    } else {
        int e = (b - MID_NS) * 8 + (t >> 5);
        int lane = t & 31;
        float a0 = ea[(size_t)e * 64 + lane];
        float a1 = ea[(size_t)e * 64 + 32 + lane];
        float dd1[4], dd2[4];
#pragma unroll
        for (int h = 0; h < 4; h++) {
            dd1[h] = a0 * d_wae1[h * 64 + lane] + a1 * d_wae1[h * 64 + 32 + lane];
            dd2[h] = a0 * d_wae2[h * 64 + lane] + a1 * d_wae2[h * 64 + 32 + lane];
            for (int o = 16; o > 0; o >>= 1) {
                dd1[h] += __shfl_xor_sync(0xffffffffu, dd1[h], o);
                dd2[h] += __shfl_xor_sync(0xffffffffu, dd2[h], o);
            }
        }
        if (lane == 0) {
            int et = d_et[e];
#pragma unroll
            for (int h = 0; h < 4; h++) {
                d_se1[e * 4 + h] = dd1[h] + d_etd1[et * 4 + h];
                d_se2[e * 4 + h] = dd2[h] + d_etd2[et * 4 + h];
            }
        }
    }
}

// ---- warp softmax stats ----
__device__ __forceinline__ void warp_softmax(const float4* se4, int beg, int end,
                                             int lane, float4 sd, float4& m, float4& rdn) {
    const float4* ssrc4 = (const float4*)d_ssrc;
    float4 mx = make_float4(-1e30f, -1e30f, -1e30f, -1e30f);
    for (int i = beg + lane; i < end; i += 32) {
        float4 l = logit4(ssrc4[d_srcS[i]], sd, se4[d_eid[i]]);
        mx.x = fmaxf(mx.x, l.x); mx.y = fmaxf(mx.y, l.y);
        mx.z = fmaxf(mx.z, l.z); mx.w = fmaxf(mx.w, l.w);
    }
    m = warpMax4(mx);
    float4 sm = make_float4(0, 0, 0, 0);
    for (int i = beg + lane; i < end; i += 32) {
        float4 l = logit4(ssrc4[d_srcS[i]], sd, se4[d_eid[i]]);
        sm.x += __expf(l.x - m.x); sm.y += __expf(l.y - m.y);
        sm.z += __expf(l.z - m.z); sm.w += __expf(l.w - m.w);
    }
    float4 den = warpSum4(sm);
    rdn.x = 1.f / (den.x + 1e-16f); rdn.y = 1.f / (den.y + 1e-16f);
    rdn.z = 1.f / (den.z + 1e-16f); rdn.w = 1.f / (den.w + 1e-16f);
}

// ---------------- K4: warp-per-node layer-1 attention (staged alphas) --------
__global__ void k_attn1(const float* __restrict__ ea, const float* __restrict__ x) {
    int wid = threadIdx.x >> 5, lane = threadIdx.x & 31;
    int n = blockIdx.x * 8 + wid;
    __shared__ ull  aSh[8][32][4];   // pre-duplicated alpha pairs
    __shared__ int2 iSh[8][32];      // (src, eid)
    __shared__ float acctSh[8][88];
    for (int i = lane; i < 88; i += 32) acctSh[wid][i] = 0.f;
    __syncwarp();
    int beg = d_off[n], end = d_off[n + 1], nE = end - beg;
    ull ax[4] = {0, 0, 0, 0}, av[4] = {0, 0, 0, 0};
    if (nE > 0) {
        const float4* ssrc4 = (const float4*)d_ssrc;
        const float4* se4 = (const float4*)d_se1;
        float4 sd = ((const float4*)d_sdst)[n];
        float4 m, rdn;
        warp_softmax(se4, beg, end, lane, sd, m, rdn);
        for (int c0 = beg; c0 < end; c0 += 32) {
            int nc = min(32, end - c0);
            if (lane < nc) {
                int i = c0 + lane;
                int s = d_srcS[i], e = d_eid[i], et = d_etS[i];
                float4 l = logit4(ssrc4[s], sd, se4[e]);
                float a0 = __expf(l.x - m.x) * rdn.x, a1 = __expf(l.y - m.y) * rdn.y;
                float a2 = __expf(l.z - m.z) * rdn.z, a3 = __expf(l.w - m.w) * rdn.w;
                aSh[wid][lane][0] = dup2(a0); aSh[wid][lane][1] = dup2(a1);
                aSh[wid][lane][2] = dup2(a2); aSh[wid][lane][3] = dup2(a3);
                iSh[wid][lane] = make_int2(s, e);
                atomicAdd(&acctSh[wid][et], a0);
                atomicAdd(&acctSh[wid][22 + et], a1);
                atomicAdd(&acctSh[wid][44 + et], a2);
                atomicAdd(&acctSh[wid][66 + et], a3);
            }
            __syncwarp();
#pragma unroll 4
            for (int j = 0; j < nc; j++) {
                ull b0 = aSh[wid][j][0], b1 = aSh[wid][j][1];
                ull b2 = aSh[wid][j][2], b3 = aSh[wid][j][3];
                int2 se = iSh[wid][j];
                ull u = *(const ull*)&d_u1[se.x * 64 + lane * 2];
                ull a = *(const ull*)&ea[(size_t)se.y * 64 + lane * 2];
                fma2(ax[0], u, b0); fma2(ax[1], u, b1);
                fma2(ax[2], u, b2); fma2(ax[3], u, b3);
                fma2(av[0], a, b0); fma2(av[1], a, b1);
                fma2(av[2], a, b2); fma2(av[3], a, b3);
            }
            __syncwarp();
        }
    }
    __syncwarp();
    float* v = &d_v1[(size_t)n * LDA1];
    int c = lane * 2;
#pragma unroll
    for (int h = 0; h < 4; h++) {
        *(ull*)&v[h * K1H + c] = ax[h];
        *(ull*)&v[h * K1H + 64 + c] = av[h];
        *(ull*)&v[h * K1H + 150 + c] = *(const ull*)&x[n * 64 + c];
    }
    for (int i = lane; i < 88; i += 32) {
        int hh = i / 22, t2 = i % 22;
        v[hh * K1H + 128 + t2] = acctSh[wid][hh * 22 + t2];
    }
    if (lane < 8) v[(lane >> 1) * K1H + 214 + (lane & 1)] = 0.f;
}

// ---------------- K6: nscore layer 2 ----------------
__global__ void k_ns2(const float* __restrict__ nte2) {
    int gw = (blockIdx.x * blockDim.x + threadIdx.x) >> 5;
    if (gw < Nn) nscore_one(gw, threadIdx.x & 31, d_h1, nte2, 256, d_wsrc2, d_wdst2, d_u2);
}

// ---------------- K7: warp-per-node layer-2 attention (staged alphas) --------
__global__ void k_attn2(const float* __restrict__ ea) {
    int wid = threadIdx.x >> 5, lane = threadIdx.x & 31;
    int n = blockIdx.x * 8 + wid;
    __shared__ ull  aSh[8][32][4];
    __shared__ int2 iSh[8][32];
    __shared__ float acctSh[8][88];
    for (int i = lane; i < 88; i += 32) acctSh[wid][i] = 0.f;
    __syncwarp();
    int beg = d_off[n], end = d_off[n + 1], nE = end - beg;
    ull axu[4][4];
#pragma unroll
    for (int h = 0; h < 4; h++)
#pragma unroll
        for (int q = 0; q < 4; q++) axu[h][q] = 0ull;
    ull av[4] = {0, 0, 0, 0};
    if (nE > 0) {
        const float4* ssrc4 = (const float4*)d_ssrc;
        const float4* se4 = (const float4*)d_se2;
        float4 sd = ((const float4*)d_sdst)[n];
        float4 m, rdn;
        warp_softmax(se4, beg, end, lane, sd, m, rdn);
        for (int c0 = beg; c0 < end; c0 += 32) {
            int nc = min(32, end - c0);
            if (lane < nc) {
                int i = c0 + lane;
                int s = d_srcS[i], e = d_eid[i], et = d_etS[i];
                float4 l = logit4(ssrc4[s], sd, se4[e]);
                float a0 = __expf(l.x - m.x) * rdn.x, a1 = __expf(l.y - m.y) * rdn.y;
                float a2 = __expf(l.z - m.z) * rdn.z, a3 = __expf(l.w - m.w) * rdn.w;
                aSh[wid][lane][0] = dup2(a0); aSh[wid][lane][1] = dup2(a1);
                aSh[wid][lane][2] = dup2(a2); aSh[wid][lane][3] = dup2(a3);
                iSh[wid][lane] = make_int2(s, e);
                atomicAdd(&acctSh[wid][et], a0);
                atomicAdd(&acctSh[wid][22 + et], a1);
                atomicAdd(&acctSh[wid][44 + et], a2);
                atomicAdd(&acctSh[wid][66 + et], a3);
            }
            __syncwarp();
#pragma unroll 2
            for (int j = 0; j < nc; j++) {
                ull b0 = aSh[wid][j][0], b1 = aSh[wid][j][1];
                ull b2 = aSh[wid][j][2], b3 = aSh[wid][j][3];
                int2 se = iSh[wid][j];
                const float4* up = (const float4*)&d_u2[se.x * 256 + lane * 8];
                float4 u0 = up[0], u1 = up[1];
                ull p0 = *(ull*)&u0.x, p1 = *(ull*)&u0.z;
                ull p2 = *(ull*)&u1.x, p3 = *(ull*)&u1.z;
                fma2(axu[0][0], p0, b0); fma2(axu[0][1], p1, b0);
                fma2(axu[0][2], p2, b0); fma2(axu[0][3], p3, b0);
                fma2(axu[1][0], p0, b1); fma2(axu[1][1], p1, b1);
                fma2(axu[1][2], p2, b1); fma2(axu[1][3], p3, b1);
                fma2(axu[2][0], p0, b2); fma2(axu[2][1], p1, b2);
                fma2(axu[2][2], p2, b2); fma2(axu[2][3], p3, b2);
                fma2(axu[3][0], p0, b3); fma2(axu[3][1], p1, b3);
                fma2(axu[3][2], p2, b3); fma2(axu[3][3], p3, b3);
                ull a = *(const ull*)&ea[(size_t)se.y * 64 + lane * 2];
                fma2(av[0], a, b0); fma2(av[1], a, b1);
                fma2(av[2], a, b2); fma2(av[3], a, b3);
            }
            __syncwarp();
        }
    }
    __syncwarp();
    float* v = &d_v2[(size_t)n * K2P];
#pragma unroll
    for (int h = 0; h < 4; h++) {
#pragma unroll
        for (int q = 0; q < 4; q++)
            *(ull*)&v[h * 256 + lane * 8 + q * 2] = axu[h][q];
        *(ull*)&v[1024 + h * 64 + lane * 2] = av[h];
    }
    for (int i = lane; i < 96; i += 32)
        v[1280 + i] = (i < 88) ? acctSh[wid][i] : 0.f;
}

// ---------------- f32x2 packed SGEMM ----------------
template <int K, int MODE>
__global__ void k_gemmT(const float* __restrict__ A, const float* __restrict__ B,
                        const float* __restrict__ bias, const float* __restrict__ add,
                        float* __restrict__ C) {
    constexpr int LDA = (MODE == 1) ? LDA1 : K2P;
    __shared__ float As[8][132];
    __shared__ float Bs[8][64];
    int y = blockIdx.y;
    int bm = blockIdx.x * 128;
    int colbase = y * 64;
    const float* Ab = A + ((MODE == 1) ? y * K1H : 0);
    const float* Bb = (MODE == 1) ? (B + y * K1H * 64) : (B + colbase);
    const int ldb = (MODE == 1) ? 64 : 256;
    int tid = threadIdx.x;
    int tx = tid & 15, ty = tid >> 4;
    int lrow = tid >> 1, lk = (tid & 1) * 4;
    int brow = tid >> 4, bcol = (tid & 15) * 4;
    ull acc[4][4];
#pragma unroll
    for (int p = 0; p < 4; p++)
#pragma unroll
        for (int j = 0; j < 4; j++) acc[p][j] = 0ull;
    for (int k0 = 0; k0 < K; k0 += 8) {
        float4 avv = make_float4(0, 0, 0, 0);
        int row = bm + lrow;
        if (row < Nn) avv = *(const float4*)&Ab[(size_t)row * LDA + k0 + lk];
        As[lk + 0][lrow] = avv.x; As[lk + 1][lrow] = avv.y;
        As[lk + 2][lrow] = avv.z; As[lk + 3][lrow] = avv.w;
        if (tid < 128) {
            float4 bv = *(const float4*)&Bb[(size_t)(k0 + brow) * ldb + bcol];
            *(float4*)&Bs[brow][bcol] = bv;
        }
        __syncthreads();
#pragma unroll
        for (int kk = 0; kk < 8; kk++) {
            ulonglong2 a01 = *(const ulonglong2*)&As[kk][ty * 8];
            ulonglong2 a23 = *(const ulonglong2*)&As[kk][ty * 8 + 4];
            float4 bv = *(const float4*)&Bs[kk][tx * 4];
            ull ap[4] = {a01.x, a01.y, a23.x, a23.y};
            ull bd[4] = {dup2(bv.x), dup2(bv.y), dup2(bv.z), dup2(bv.w)};
#pragma unroll
            for (int p = 0; p < 4; p++)
#pragma unroll
                for (int j = 0; j < 4; j++) fma2(acc[p][j], ap[p], bd[j]);
        }
        __syncthreads();
    }
#pragma unroll
    for (int p = 0; p < 4; p++) {
        int r0 = bm + ty * 8 + 2 * p;
#pragma unroll
        for (int j = 0; j < 4; j++) {
            int col = colbase + tx * 4 + j;
            float lo = __uint_as_float((unsigned)(acc[p][j] & 0xffffffffull));
            float hi = __uint_as_float((unsigned)(acc[p][j] >> 32));
            float bsv = bias[col];
            if (r0 < Nn) {
                float v = lo + bsv;
                if (MODE == 1) v = fmaxf(v, 0.f);
                else v += add[r0 * 256 + col];
                C[r0 * 256 + col] = v;
            }
            if (r0 + 1 < Nn) {
                float v = hi + bsv;
                if (MODE == 1) v = fmaxf(v, 0.f);
                else v += add[(r0 + 1) * 256 + col];
                C[(r0 + 1) * 256 + col] = v;
            }
        }
    }
}

// ---------------- launch ----------------
extern "C" void kernel_launch(void* const* d_in, const int* in_sizes, int n_in,
                              void* d_out, int out_size) {
    const float* x    = (const float*)d_in[0];
    const void*  ei   = d_in[1];
    const void*  ntp  = d_in[2];
    const float* ea   = (const float*)d_in[3];
    const void*  etp  = d_in[4];
    const float* W1   = (const float*)d_in[5];
    const float* b1   = (const float*)d_in[6];
    const float* We1  = (const float*)d_in[7];
    const float* nte1 = (const float*)d_in[8];
    const float* ete1 = (const float*)d_in[9];
    const float* as1  = (const float*)d_in[10];
    const float* ad1  = (const float*)d_in[11];
    const float* ag1  = (const float*)d_in[12];
    const float* res1 = (const float*)d_in[13];
    const float* W2   = (const float*)d_in[14];
    const float* b2   = (const float*)d_in[15];
    const float* We2  = (const float*)d_in[16];
    const float* nte2 = (const float*)d_in[17];
    const float* ete2 = (const float*)d_in[18];
    const float* as2  = (const float*)d_in[19];
    const float* ad2  = (const float*)d_in[20];
    const float* ag2  = (const float*)d_in[21];
    float* out = (float*)d_out;

    k_pre<<<PRE_TOT, 256>>>(ei, ntp, etp, W1, as1, ad1, We1, ag1, ete1,
                            W2, as2, ad2, We2, ag2, ete2, res1);
    k_scan<<<1, 1024>>>();
    k_mid<<<MID_TOT, 256>>>(ea, x, nte1);
    k_attn1<<<Nn / 8, 256>>>(ea, x);

    float* h1;  cudaGetSymbolAddress((void**)&h1, d_h1);
    float* v1;  cudaGetSymbolAddress((void**)&v1, d_v1);
    float* w1h; cudaGetSymbolAddress((void**)&w1h, d_W1h);
    float* v2;  cudaGetSymbolAddress((void**)&v2, d_v2);
    float* w2c; cudaGetSymbolAddress((void**)&w2c, d_W2cat);
    dim3 g((Nn + 127) / 128, 4);
    k_gemmT<K1H, 1><<<g, 256>>>(v1, w1h, b1, nullptr, h1);
    k_ns2<<<(Nn * 32 + 255) / 256, 256>>>(nte2);
    k_attn2<<<Nn / 8, 256>>>(ea);
    k_gemmT<K2P, 2><<<g, 256>>>(v2, w2c, b2, h1, out);
}